// round 3
// baseline (speedup 1.0000x reference)
#include <cuda_runtime.h>
#include <math.h>
#include <stdint.h>

#define E_EDGES 65536
#define N_NODES 4096

// ---------------- device scratch ----------------
__device__ float g_w3j[678];
__device__ float g_shc[2];
__device__ float g_w[E_EDGES * 64];
__device__ float g_Y[E_EDGES * 16];
__device__ float g_len[E_EDGES];
__device__ int   g_cnt[N_NODES];
__device__ int   g_off[N_NODES + 1];
__device__ int   g_cursor[N_NODES];
__device__ int   g_sorted[E_EDGES];
__device__ float g_nodewY[N_NODES * 1024];
__device__ float g_S[E_EDGES * 192];
__device__ float g_A1[(size_t)E_EDGES * 3 * 320];
__device__ float g_A2[(size_t)E_EDGES * 5 * 320];

// w3j path table offsets:
// 0:(0,0,0) 1:(1,1,0) 2:(2,2,0) 3:(0,1,1) 4:(1,0,1) 5:(1,2,1) 6:(2,1,1)
// 7:(3,2,1) 8:(0,2,2) 9:(1,1,2) 10:(2,0,2) 11:(2,2,2) 12:(3,1,2) 13:(2,1,3)
// offsets: 0,1,10,35,44,53,98,143,248,273,318,343,468,573 ; total 678

__device__ double dfact(int n) {
    double r = 1.0;
    for (int i = 2; i <= n; ++i) r *= (double)i;
    return r;
}

__device__ double su2_cg(int j1, int j2, int j3, int m1, int m2, int m3) {
    if (m3 != m1 + m2) return 0.0;
    double pref = sqrt((2.0 * j3 + 1.0) * dfact(j3 + j1 - j2) * dfact(j3 - j1 + j2) *
                       dfact(j1 + j2 - j3) / dfact(j1 + j2 + j3 + 1));
    pref *= sqrt(dfact(j3 + m3) * dfact(j3 - m3) * dfact(j1 - m1) * dfact(j1 + m1) *
                 dfact(j2 - m2) * dfact(j2 + m2));
    double s = 0.0;
    for (int k = 0; k <= j1 + j2 - j3; ++k) {
        int d0 = k, d1 = j1 + j2 - j3 - k, d2 = j1 - m1 - k, d3 = j2 + m2 - k;
        int d4 = j3 - j2 + m1 + k, d5 = j3 - j1 - m2 + k;
        if (d0 < 0 || d1 < 0 || d2 < 0 || d3 < 0 || d4 < 0 || d5 < 0) continue;
        double den = dfact(d0) * dfact(d1) * dfact(d2) * dfact(d3) * dfact(d4) * dfact(d5);
        s += ((k & 1) ? -1.0 : 1.0) / den;
    }
    return pref * s;
}

__device__ void build_q(int l, double* qr, double* qi) {
    for (int i = 0; i < 49; ++i) { qr[i] = 0.0; qi[i] = 0.0; }
    const double is2 = 0.70710678118654752440;
    for (int m = -l; m < 0; ++m) {
        qr[(l + m) * 7 + (l - m)] = is2;
        qi[(l + m) * 7 + (l + m)] = -is2;
    }
    qr[l * 7 + l] = 1.0;
    for (int m = 1; m <= l; ++m) {
        double sg = (m & 1) ? -1.0 : 1.0;
        qr[(l + m) * 7 + (l + m)] = sg * is2;
        qi[(l + m) * 7 + (l - m)] = sg * is2;
    }
    // multiply by (-i)^l
    int lm = l & 3;
    double pr, pi;
    if (lm == 0) { pr = 1; pi = 0; }
    else if (lm == 1) { pr = 0; pi = -1; }
    else if (lm == 2) { pr = -1; pi = 0; }
    else { pr = 0; pi = 1; }
    for (int i = 0; i < 49; ++i) {
        double r = qr[i], im = qi[i];
        qr[i] = pr * r - pi * im;
        qi[i] = pr * im + pi * r;
    }
}

__global__ void w3j_kernel() {
    const int L1[14] = {0, 1, 2, 0, 1, 1, 2, 3, 0, 1, 2, 2, 3, 2};
    const int L2[14] = {0, 1, 2, 1, 0, 2, 1, 2, 2, 1, 0, 2, 1, 1};
    const int L3[14] = {0, 0, 0, 1, 1, 1, 1, 1, 2, 2, 2, 2, 2, 3};
    const int OFFS[14] = {0, 1, 10, 35, 44, 53, 98, 143, 248, 273, 318, 343, 468, 573};
    int p = blockIdx.x;
    int t = threadIdx.x;
    int l1 = L1[p], l2 = L2[p], l3 = L3[p];
    int n1 = 2 * l1 + 1, n2 = 2 * l2 + 1, n3 = 2 * l3 + 1;
    int ntot = n1 * n2 * n3;

    __shared__ double sC[125];
    __shared__ double q1r[49], q1i[49], q2r[49], q2i[49], q3r[49], q3i[49];
    __shared__ double red[128];

    if (t < ntot) {
        int a = t / (n2 * n3);
        int b = (t / n3) % n2;
        int c = t % n3;
        sC[t] = su2_cg(l1, l2, l3, a - l1, b - l2, c - l3);
    }
    if (t == 0) {
        build_q(l1, q1r, q1i);
        build_q(l2, q2r, q2i);
        build_q(l3, q3r, q3i);
    }
    __syncthreads();

    double cr = 0.0;
    if (t < ntot) {
        int i = t / (n2 * n3);
        int j = (t / n3) % n2;
        int k = t % n3;
        for (int a = 0; a < n1; ++a) {
            double ar = q1r[a * 7 + i], ai = q1i[a * 7 + i];
            for (int b = 0; b < n2; ++b) {
                double br = q2r[b * 7 + j], bi = q2i[b * 7 + j];
                double tr = ar * br - ai * bi;
                double ti = ar * bi + ai * br;
                for (int c = 0; c < n3; ++c) {
                    double c3r = q3r[c * 7 + k], c3i = q3i[c * 7 + k];
                    double re = tr * c3r + ti * c3i;   // real(T * conj(C3))
                    cr += re * sC[(a * n2 + b) * n3 + c];
                }
            }
        }
    }
    red[t] = (t < ntot) ? cr * cr : 0.0;
    __syncthreads();
    for (int s = 64; s > 0; s >>= 1) {
        if (t < s) red[t] += red[t + s];
        __syncthreads();
    }
    double inv = 1.0 / sqrt(red[0]);
    if (t < ntot) g_w3j[OFFS[p] + t] = (float)(cr * inv);
}

__global__ void shc_kernel() {
    double u0[3] = {0.3, -0.4, sqrt(0.75)};
    double y1[3];
    for (int i = 0; i < 3; ++i) y1[i] = sqrt(3.0) * u0[i];
    double y2r[5] = {0, 0, 0, 0, 0};
    for (int i = 0; i < 3; ++i)
        for (int j = 0; j < 3; ++j)
            for (int k = 0; k < 5; ++k)
                y2r[k] += y1[i] * y1[j] * (double)g_w3j[273 + (i * 3 + j) * 5 + k];
    double n2s = 0;
    for (int k = 0; k < 5; ++k) n2s += y2r[k] * y2r[k];
    double c2 = sqrt(5.0) / sqrt(n2s);
    double y3r[7] = {0, 0, 0, 0, 0, 0, 0};
    for (int i = 0; i < 5; ++i)
        for (int j = 0; j < 3; ++j)
            for (int k = 0; k < 7; ++k)
                y3r[k] += (c2 * y2r[i]) * y1[j] * (double)g_w3j[573 + (i * 3 + j) * 7 + k];
    double n3s = 0;
    for (int k = 0; k < 7; ++k) n3s += y3r[k] * y3r[k];
    double c3 = sqrt(7.0) / sqrt(n3s);
    g_shc[0] = (float)c2;
    g_shc[1] = (float)c3;
}

__global__ void zero_cnt_kernel() {
    int i = blockIdx.x * blockDim.x + threadIdx.x;
    if (i < N_NODES) g_cnt[i] = 0;
}

// ------------- edge pre: w = x@Ww/8, Y(16), len, histogram -------------
__global__ __launch_bounds__(256) void edge_pre_kernel(
    const float* __restrict__ vectors, const float* __restrict__ x,
    const float* __restrict__ Ww, const int* __restrict__ senders) {
    __shared__ float sx[4][64];
    __shared__ float sWw[4096];
    int t = threadIdx.x;
    int slot = t >> 6, u = t & 63;
    int e = blockIdx.x * 4 + slot;
    sx[slot][u] = x[e * 64 + u];
    for (int i = t; i < 4096; i += 256) sWw[i] = Ww[i];
    __syncthreads();
    float acc = 0.f;
#pragma unroll
    for (int f = 0; f < 64; ++f) acc += sx[slot][f] * sWw[f * 64 + u];
    g_w[e * 64 + u] = acc * 0.125f;

    if (u < 16) {
        float vx = vectors[e * 3 + 0], vy = vectors[e * 3 + 1], vz = vectors[e * 3 + 2];
        float len = sqrtf(vx * vx + vy * vy + vz * vz);
        float inv = 1.0f / (len + 1e-12f);
        float y1[3] = {1.7320508075688772f * vx * inv,
                       1.7320508075688772f * vy * inv,
                       1.7320508075688772f * vz * inv};
        float C2 = g_shc[0], C3 = g_shc[1];
        float y2[5] = {0, 0, 0, 0, 0};
#pragma unroll
        for (int i = 0; i < 3; ++i)
#pragma unroll
            for (int j = 0; j < 3; ++j) {
                float ab = y1[i] * y1[j];
#pragma unroll
                for (int k = 0; k < 5; ++k) y2[k] += ab * g_w3j[273 + (i * 3 + j) * 5 + k];
            }
#pragma unroll
        for (int k = 0; k < 5; ++k) y2[k] *= C2;
        float Yv;
        if (u == 0) Yv = 1.0f;
        else if (u < 4) Yv = y1[u - 1];
        else if (u < 9) Yv = y2[u - 4];
        else {
            int k = u - 9;
            float s = 0.f;
#pragma unroll
            for (int i = 0; i < 5; ++i)
#pragma unroll
                for (int j = 0; j < 3; ++j)
                    s += y2[i] * y1[j] * g_w3j[573 + (i * 3 + j) * 7 + k];
            Yv = C3 * s;
        }
        g_Y[e * 16 + u] = Yv;
        if (u == 0) {
            g_len[e] = len;
            atomicAdd(&g_cnt[senders[e]], 1);
        }
    }
}

// ------------- exclusive scan of 4096 counts, one block -------------
__global__ void scan_kernel() {
    int t = threadIdx.x;
    int b = t * 4;
    int v0 = g_cnt[b], v1 = g_cnt[b + 1], v2 = g_cnt[b + 2], v3 = g_cnt[b + 3];
    int tsum = v0 + v1 + v2 + v3;
    int xv = tsum;
#pragma unroll
    for (int o = 1; o < 32; o <<= 1) {
        int y = __shfl_up_sync(0xffffffffu, xv, o);
        if ((t & 31) >= o) xv += y;
    }
    __shared__ int wsum[32];
    if ((t & 31) == 31) wsum[t >> 5] = xv;
    __syncthreads();
    if (t < 32) {
        int z = wsum[t];
#pragma unroll
        for (int o = 1; o < 32; o <<= 1) {
            int y = __shfl_up_sync(0xffffffffu, z, o);
            if (t >= o) z += y;
        }
        wsum[t] = z;
    }
    __syncthreads();
    int excl = xv - tsum + ((t >= 32) ? wsum[(t >> 5) - 1] : 0);
    int run = excl;
    g_off[b] = run; g_cursor[b] = run; run += v0;
    g_off[b + 1] = run; g_cursor[b + 1] = run; run += v1;
    g_off[b + 2] = run; g_cursor[b + 2] = run; run += v2;
    g_off[b + 3] = run; g_cursor[b + 3] = run; run += v3;
    if (t == 1023) g_off[N_NODES] = run;
}

__global__ void scatter_kernel(const int* __restrict__ senders) {
    int e = blockIdx.x * blockDim.x + threadIdx.x;
    int pos = atomicAdd(&g_cursor[senders[e]], 1);
    g_sorted[pos] = e;
}

// ------------- per-node accumulate eps * sum_e w (x) Y -------------
__global__ __launch_bounds__(256) void node_accum_kernel() {
    int n = blockIdx.x, t = threadIdx.x;
    int s = g_off[n];
    int cnt = g_off[n + 1] - s;
    int uu = t >> 4, ii = t & 15;
    __shared__ float sw[64];
    __shared__ float sy[16];
    float a0 = 0, a1 = 0, a2 = 0, a3 = 0;
    for (int q = 0; q < cnt; ++q) {
        int e = g_sorted[s + q];
        __syncthreads();
        if (t < 64) sw[t] = g_w[e * 64 + t];
        else if (t < 80) sy[t - 64] = g_Y[e * 16 + (t - 64)];
        __syncthreads();
        float yv = sy[ii];
        a0 += sw[uu] * yv;
        a1 += sw[uu + 16] * yv;
        a2 += sw[uu + 32] * yv;
        a3 += sw[uu + 48] * yv;
    }
    float* dst = &g_nodewY[n * 1024];
    dst[uu * 16 + ii] = 0.25f * a0;
    dst[(uu + 16) * 16 + ii] = 0.25f * a1;
    dst[(uu + 32) * 16 + ii] = 0.25f * a2;
    dst[(uu + 48) * 16 + ii] = 0.25f * a3;
}

// ------------- main edge kernel: 13 TP paths -> S, A1(P), A2(D) -------------
__global__ __launch_bounds__(256) void edge_main_kernel(
    const float* __restrict__ V, const int* __restrict__ senders) {
    __shared__ float sw3j[678];
    int t = threadIdx.x;
    for (int i = t; i < 678; i += 256) sw3j[i] = g_w3j[i];
    int slot = t >> 6, u = t & 63;
    int e = blockIdx.x * 4 + slot;
    int n = senders[e];
    __syncthreads();

    float wy[16];
    {
        const float4* wp = (const float4*)&g_nodewY[n * 1024 + u * 16];
        float4 q0 = wp[0], q1 = wp[1], q2 = wp[2], q3 = wp[3];
        wy[0] = q0.x; wy[1] = q0.y; wy[2] = q0.z; wy[3] = q0.w;
        wy[4] = q1.x; wy[5] = q1.y; wy[6] = q1.z; wy[7] = q1.w;
        wy[8] = q2.x; wy[9] = q2.y; wy[10] = q2.z; wy[11] = q2.w;
        wy[12] = q3.x; wy[13] = q3.y; wy[14] = q3.z; wy[15] = q3.w;
    }
    const float* Vr = V + (size_t)e * 576;
    float v0 = Vr[u];
    float v1[3], v2[5];
#pragma unroll
    for (int j = 0; j < 3; ++j) v1[j] = Vr[64 + u * 3 + j];
#pragma unroll
    for (int j = 0; j < 5; ++j) v2[j] = Vr[256 + u * 5 + j];

    // scalar paths (l3 = 0, coef 1)
    float s0 = wy[0] * v0 * sw3j[0];
    float s1 = 0.f;
#pragma unroll
    for (int i = 0; i < 3; ++i)
#pragma unroll
        for (int j = 0; j < 3; ++j) s1 += wy[1 + i] * v1[j] * sw3j[1 + i * 3 + j];
    float s2 = 0.f;
#pragma unroll
    for (int i = 0; i < 5; ++i)
#pragma unroll
        for (int j = 0; j < 5; ++j) s2 += wy[4 + i] * v2[j] * sw3j[10 + i * 5 + j];
    g_S[e * 192 + u] = s0;
    g_S[e * 192 + 64 + u] = s1;
    g_S[e * 192 + 128 + u] = s2;

    // l3 = 1 paths (coef sqrt(3))
    float p[5][3];
#pragma unroll
    for (int pa = 0; pa < 5; ++pa)
#pragma unroll
        for (int k = 0; k < 3; ++k) p[pa][k] = 0.f;
#pragma unroll
    for (int j = 0; j < 3; ++j) {
        float ab = wy[0] * v1[j];
#pragma unroll
        for (int k = 0; k < 3; ++k) p[0][k] += ab * sw3j[35 + j * 3 + k];
    }
#pragma unroll
    for (int i = 0; i < 3; ++i) {
        float ab = wy[1 + i] * v0;
#pragma unroll
        for (int k = 0; k < 3; ++k) p[1][k] += ab * sw3j[44 + i * 3 + k];
    }
#pragma unroll
    for (int i = 0; i < 3; ++i)
#pragma unroll
        for (int j = 0; j < 5; ++j) {
            float ab = wy[1 + i] * v2[j];
#pragma unroll
            for (int k = 0; k < 3; ++k) p[2][k] += ab * sw3j[53 + (i * 5 + j) * 3 + k];
        }
#pragma unroll
    for (int i = 0; i < 5; ++i)
#pragma unroll
        for (int j = 0; j < 3; ++j) {
            float ab = wy[4 + i] * v1[j];
#pragma unroll
            for (int k = 0; k < 3; ++k) p[3][k] += ab * sw3j[98 + (i * 3 + j) * 3 + k];
        }
#pragma unroll
    for (int i = 0; i < 7; ++i)
#pragma unroll
        for (int j = 0; j < 5; ++j) {
            float ab = wy[9 + i] * v2[j];
#pragma unroll
            for (int k = 0; k < 3; ++k) p[4][k] += ab * sw3j[143 + (i * 5 + j) * 3 + k];
        }

    // l3 = 2 paths (coef sqrt(5))
    float dd[5][5];
#pragma unroll
    for (int pa = 0; pa < 5; ++pa)
#pragma unroll
        for (int k = 0; k < 5; ++k) dd[pa][k] = 0.f;
#pragma unroll
    for (int j = 0; j < 5; ++j) {
        float ab = wy[0] * v2[j];
#pragma unroll
        for (int k = 0; k < 5; ++k) dd[0][k] += ab * sw3j[248 + j * 5 + k];
    }
#pragma unroll
    for (int i = 0; i < 3; ++i)
#pragma unroll
        for (int j = 0; j < 3; ++j) {
            float ab = wy[1 + i] * v1[j];
#pragma unroll
            for (int k = 0; k < 5; ++k) dd[1][k] += ab * sw3j[273 + (i * 3 + j) * 5 + k];
        }
#pragma unroll
    for (int i = 0; i < 5; ++i) {
        float ab = wy[4 + i] * v0;
#pragma unroll
        for (int k = 0; k < 5; ++k) dd[2][k] += ab * sw3j[318 + i * 5 + k];
    }
#pragma unroll
    for (int i = 0; i < 5; ++i)
#pragma unroll
        for (int j = 0; j < 5; ++j) {
            float ab = wy[4 + i] * v2[j];
#pragma unroll
            for (int k = 0; k < 5; ++k) dd[3][k] += ab * sw3j[343 + (i * 5 + j) * 5 + k];
        }
#pragma unroll
    for (int i = 0; i < 7; ++i)
#pragma unroll
        for (int j = 0; j < 3; ++j) {
            float ab = wy[9 + i] * v1[j];
#pragma unroll
            for (int k = 0; k < 5; ++k) dd[4][k] += ab * sw3j[468 + (i * 3 + j) * 5 + k];
        }

    const float SQ3 = 1.7320508075688772f;
    const float SQ5 = 2.2360679774997896f;
#pragma unroll
    for (int k = 0; k < 3; ++k) {
        size_t rb = ((size_t)e * 3 + k) * 320;
#pragma unroll
        for (int pa = 0; pa < 5; ++pa)
            g_A1[rb + pa * 64 + u] = SQ3 * p[pa][k];
    }
#pragma unroll
    for (int k = 0; k < 5; ++k) {
        size_t rb = ((size_t)e * 5 + k) * 320;
#pragma unroll
        for (int pa = 0; pa < 5; ++pa)
            g_A2[rb + pa * 64 + u] = SQ5 * dd[pa][k];
    }
}

// ------------- fused 3-layer MLP + envelope -> out[:, 0:64] -------------
__global__ __launch_bounds__(256) void mlp_kernel(
    const float* __restrict__ x, const float* __restrict__ W1,
    const float* __restrict__ W2, const float* __restrict__ W3,
    float* __restrict__ out) {
    extern __shared__ float smem[];
    float* sW1 = smem;              // 16384
    float* sW2 = smem + 16384;      // 4096
    float* sW3 = smem + 20480;      // 4096
    float* shh = smem + 24576;      // 4*256
    float* sh1 = smem + 25600;      // 4*64
    float* sh2 = smem + 25856;      // 4*64 (end 26112 floats)
    int t = threadIdx.x;
    for (int i = t; i < 16384; i += 256) sW1[i] = W1[i];
    for (int i = t; i < 4096; i += 256) { sW2[i] = W2[i]; sW3[i] = W3[i]; }
    __syncthreads();

    int s = t >> 6, u = t & 63;
    for (int it = 0; it < 32; ++it) {
        int ebase = blockIdx.x * 128 + it * 4;
        for (int l = 0; l < 4; ++l) {
            int f = t + l * 256;
            int es = ebase + (f >> 8);
            int idx = f & 255;
            shh[f] = (idx < 64) ? x[es * 64 + idx] : g_S[es * 192 + idx - 64];
        }
        __syncthreads();
        int e = ebase + s;
        float a1 = 0.f;
#pragma unroll 8
        for (int f = 0; f < 256; ++f) a1 += shh[s * 256 + f] * sW1[f * 64 + u];
        a1 *= 0.0625f;
        float h1 = a1 / (1.f + expf(-a1));
        sh1[s * 64 + u] = h1;
        __syncthreads();
        float a2 = 0.f;
#pragma unroll 8
        for (int f = 0; f < 64; ++f) a2 += sh1[s * 64 + f] * sW2[f * 64 + u];
        a2 *= 0.125f;
        float h2 = a2 / (1.f + expf(-a2));
        sh2[s * 64 + u] = h2;
        __syncthreads();
        float a3 = 0.f;
#pragma unroll 8
        for (int f = 0; f < 64; ++f) a3 += sh2[s * 64 + f] * sW3[f * 64 + u];
        a3 *= 0.125f;
        float d = g_len[e];
        float d2 = d * d, d3 = d2 * d;
        float d6 = d3 * d3, d7 = d6 * d, d8 = d7 * d;
        float env = (d < 1.0f) ? (1.0f - 28.0f * d6 + 48.0f * d7 - 21.0f * d8) : 0.0f;
        out[(size_t)e * 576 + u] = env * a3;
        __syncthreads();
    }
}

// ------------- tiled GEMM: C(M,64) = alpha * A(M,320) @ B(320,64) -------------
// mode 0: A = g_A1, row r -> e=r/3, i=r%3, out[e*576 + 64  + c*3 + i]
// mode 1: A = g_A2, row r -> e=r/5, i=r%5, out[e*576 + 256 + c*5 + i]
__global__ __launch_bounds__(256) void gemm_kernel(
    const float* __restrict__ B, float* __restrict__ out, int mode) {
    const float* __restrict__ A = (mode == 0) ? g_A1 : g_A2;  // device-side symbol ref
    __shared__ float sA[32 * 129];   // [k][row], stride 129 (conflict-free)
    __shared__ float sB[32 * 64];    // [k][col]
    int t = threadIdx.x;
    int tr = t >> 4, tc = t & 15;
    int row0 = blockIdx.x * 128;
    float acc[8][4];
#pragma unroll
    for (int r = 0; r < 8; ++r)
#pragma unroll
        for (int j = 0; j < 4; ++j) acc[r][j] = 0.f;

    for (int kt = 0; kt < 10; ++kt) {
#pragma unroll
        for (int l = 0; l < 4; ++l) {
            int f = t + l * 256;           // 0..1023 float4s
            int row = f >> 3, kq = f & 7;
            float4 v = *(const float4*)(A + (size_t)(row0 + row) * 320 + kt * 32 + kq * 4);
            int k0 = kq * 4;
            sA[(k0 + 0) * 129 + row] = v.x;
            sA[(k0 + 1) * 129 + row] = v.y;
            sA[(k0 + 2) * 129 + row] = v.z;
            sA[(k0 + 3) * 129 + row] = v.w;
        }
#pragma unroll
        for (int l = 0; l < 2; ++l) {
            int f = t + l * 256;           // 0..511 float4s
            int k = f >> 4, cq = f & 15;
            float4 v = *(const float4*)(B + (kt * 32 + k) * 64 + cq * 4);
            *(float4*)(sB + k * 64 + cq * 4) = v;
        }
        __syncthreads();
#pragma unroll
        for (int k = 0; k < 32; ++k) {
            float bv0 = sB[k * 64 + tc * 4 + 0];
            float bv1 = sB[k * 64 + tc * 4 + 1];
            float bv2 = sB[k * 64 + tc * 4 + 2];
            float bv3 = sB[k * 64 + tc * 4 + 3];
#pragma unroll
            for (int r = 0; r < 8; ++r) {
                float a = sA[k * 129 + tr * 8 + r];
                acc[r][0] += a * bv0;
                acc[r][1] += a * bv1;
                acc[r][2] += a * bv2;
                acc[r][3] += a * bv3;
            }
        }
        __syncthreads();
    }

    const float alpha = 0.05590169943749474f;  // 1/sqrt(320)
#pragma unroll
    for (int r = 0; r < 8; ++r) {
        int gr = row0 + tr * 8 + r;
        if (mode == 0) {
            int e = gr / 3, i = gr - e * 3;
            size_t base = (size_t)e * 576 + 64 + i;
#pragma unroll
            for (int j = 0; j < 4; ++j)
                out[base + (size_t)(tc * 4 + j) * 3] = alpha * acc[r][j];
        } else {
            int e = gr / 5, i = gr - e * 5;
            size_t base = (size_t)e * 576 + 256 + i;
#pragma unroll
            for (int j = 0; j < 4; ++j)
                out[base + (size_t)(tc * 4 + j) * 5] = alpha * acc[r][j];
        }
    }
}

extern "C" void kernel_launch(void* const* d_in, const int* in_sizes, int n_in,
                              void* d_out, int out_size) {
    const float* vectors = (const float*)d_in[0];
    const float* x       = (const float*)d_in[1];
    const float* V       = (const float*)d_in[2];
    const int*   senders = (const int*)d_in[3];
    const float* Ww      = (const float*)d_in[4];
    const float* W1      = (const float*)d_in[5];
    const float* W2      = (const float*)d_in[6];
    const float* W3      = (const float*)d_in[7];
    const float* Wl1     = (const float*)d_in[8];
    const float* Wl2     = (const float*)d_in[9];
    float* out = (float*)d_out;

    cudaFuncSetAttribute(mlp_kernel, cudaFuncAttributeMaxDynamicSharedMemorySize,
                         26112 * 4);

    w3j_kernel<<<14, 128>>>();
    shc_kernel<<<1, 1>>>();
    zero_cnt_kernel<<<16, 256>>>();
    edge_pre_kernel<<<E_EDGES / 4, 256>>>(vectors, x, Ww, senders);
    scan_kernel<<<1, 1024>>>();
    scatter_kernel<<<E_EDGES / 1024, 1024>>>(senders);
    node_accum_kernel<<<N_NODES, 256>>>();
    edge_main_kernel<<<E_EDGES / 4, 256>>>(V, senders);
    mlp_kernel<<<512, 256, 26112 * 4>>>(x, W1, W2, W3, out);
    gemm_kernel<<<(E_EDGES * 3) / 128, 256>>>(Wl1, out, 0);
    gemm_kernel<<<(E_EDGES * 5) / 128, 256>>>(Wl2, out, 1);
}